// round 1
// baseline (speedup 1.0000x reference)
#include <cuda_runtime.h>
#include <math.h>

// Problem constants (fixed shapes: pred/target = [4,1,96,96,96] fp32)
#define NB      23          // bins
#define NBP     24          // padded bins
#define NPAIR   12          // bin pairs (24/2)
#define BLOCK_T 144         // threads per block = 12x12 grid of 2x2 tiles
#define SSTRIDE 145         // shared row stride (float2 elems), pad vs bank conflicts
#define ITERS   16          // stage iterations per block
#define NBLK    384         // blocks per batch: 384*16*144 = 884736 exactly
#define BATCH   4
#define NVOX    884736      // 96^3
#define CELLS   (NBP*NBP)   // 576

// Scratch (static device globals -- no allocation allowed)
__device__ float  g_partial[(size_t)BATCH * CELLS * NBLK];  // [b][cell][blk], 3.54 MB
__device__ double g_pab[BATCH * CELLS];
__device__ double g_mi[BATCH];

// -968 * log2(e)
#define K2EXP (-1396.5287995805166f)

__global__ __launch_bounds__(BLOCK_T)
void mi_partial_kernel(const float* __restrict__ pred,
                       const float* __restrict__ target)
{
    __shared__ float2 waS[NPAIR][SSTRIDE];
    __shared__ float2 wbS[NPAIR][SSTRIDE];

    const int tid = threadIdx.x;
    const int b   = blockIdx.y;
    const int blk = blockIdx.x;
    const int tx  = tid % NPAIR;   // j pair index
    const int ty  = tid / NPAIR;   // i pair index

    const float* __restrict__ px = pred   + (size_t)b * NVOX;
    const float* __restrict__ py = target + (size_t)b * NVOX;
    const int base = blk * (ITERS * BLOCK_T);

    double d00 = 0.0, d01 = 0.0, d10 = 0.0, d11 = 0.0;

    for (int it = 0; it < ITERS; ++it) {
        const int idx = base + it * BLOCK_T + tid;
        float x = px[idx]; x = fminf(fmaxf(x, 0.0f), 1.0f);
        float y = py[idx]; y = fminf(fmaxf(y, 0.0f), 1.0f);

        // dense Parzen weights (all 23 bins, exact vs reference)
        float wa[NB]; float Sa = 0.0f;
        #pragma unroll
        for (int i = 0; i < NB; ++i) {
            const float ci = (float)(i * (1.0 / 22.0));
            const float d  = x - ci;
            wa[i] = exp2f(K2EXP * d * d);
            Sa += wa[i];
        }
        float wb[NB]; float Sb = 0.0f;
        #pragma unroll
        for (int i = 0; i < NB; ++i) {
            const float ci = (float)(i * (1.0 / 22.0));
            const float d  = y - ci;
            wb[i] = exp2f(K2EXP * d * d);
            Sb += wb[i];
        }
        // correctly-rounded reciprocal (bias of fast rcp would exceed error budget)
        const float rs = 1.0f / (Sa * Sb);

        #pragma unroll
        for (int k = 0; k < NPAIR; ++k) {
            const float ax = wa[2 * k];
            const float ay = (2 * k + 1 < NB) ? wa[2 * k + 1] : 0.0f;
            waS[k][tid] = make_float2(ax, ay);
            const float bx = wb[2 * k] * rs;
            const float by = (2 * k + 1 < NB) ? wb[2 * k + 1] * rs : 0.0f;
            wbS[k][tid] = make_float2(bx, by);
        }
        __syncthreads();

        // 2x2 register-tiled outer-product accumulation over 144 staged voxels
        float a00 = 0.0f, a01 = 0.0f, a10 = 0.0f, a11 = 0.0f;
        const float2* __restrict__ ra = &waS[ty][0];
        const float2* __restrict__ rb = &wbS[tx][0];
        #pragma unroll 4
        for (int t = 0; t < BLOCK_T; ++t) {
            const float2 va = ra[t];
            const float2 vb = rb[t];
            a00 = fmaf(va.x, vb.x, a00);
            a01 = fmaf(va.x, vb.y, a01);
            a10 = fmaf(va.y, vb.x, a10);
            a11 = fmaf(va.y, vb.y, a11);
        }
        __syncthreads();

        // flush fp32 accumulators to fp64 each stage (keeps per-cell error ~1e-11)
        d00 += (double)a00; d01 += (double)a01;
        d10 += (double)a10; d11 += (double)a11;
    }

    // write partials: layout [b][cell][blk] so the reduce kernel reads coalesced
    float* out = g_partial + (size_t)b * CELLS * NBLK;
    const int i0 = 2 * ty, j0 = 2 * tx;
    out[(size_t)((i0    ) * NBP + j0    ) * NBLK + blk] = (float)d00;
    out[(size_t)((i0    ) * NBP + j0 + 1) * NBLK + blk] = (float)d01;
    out[(size_t)((i0 + 1) * NBP + j0    ) * NBLK + blk] = (float)d10;
    out[(size_t)((i0 + 1) * NBP + j0 + 1) * NBLK + blk] = (float)d11;
}

// Stage-1 reduce: one warp per (batch, cell); lanes read coalesced over blocks.
__global__ void mi_reduce1_kernel()
{
    const int b    = blockIdx.y;
    const int w    = threadIdx.x >> 5;
    const int lane = threadIdx.x & 31;
    const int c    = blockIdx.x * 32 + w;   // grid.x = 18 -> 576 cells

    const float* __restrict__ p = g_partial + ((size_t)b * CELLS + c) * NBLK;
    float s = 0.0f;
    for (int k = lane; k < NBLK; k += 32) s += p[k];
    double d = (double)s;
    #pragma unroll
    for (int o = 16; o > 0; o >>= 1)
        d += __shfl_down_sync(0xffffffffu, d, o);
    if (lane == 0) g_pab[b * CELLS + c] = d;
}

// Stage-2: marginals (exact row/col sums of pab) + MI in double. One block per batch.
__global__ void mi_reduce2_kernel()
{
    const int b = blockIdx.x;
    const int c = threadIdx.x;  // 0..575
    __shared__ double pabS[CELLS];
    __shared__ double paS[NBP], pbS[NBP];
    __shared__ double red[CELLS];

    pabS[c] = g_pab[b * CELLS + c];
    __syncthreads();

    const double invN = 1.0 / (double)NVOX;
    if (c < NB) {
        double t = 0.0;
        for (int j = 0; j < NB; ++j) t += pabS[c * NBP + j];
        paS[c] = t * invN;
    } else if (c >= 32 && c < 32 + NB) {
        const int j = c - 32;
        double t = 0.0;
        for (int i = 0; i < NB; ++i) t += pabS[i * NBP + j];
        pbS[j] = t * invN;
    }
    __syncthreads();

    const int i = c / NBP, j = c % NBP;
    double term = 0.0;
    if (i < NB && j < NB) {
        const double pab  = pabS[c] * invN;
        const double papb = paS[i] * pbS[j];
        term = pab * log((pab + 1e-7) / (papb + 1e-7) + 1e-7);
    }
    red[c] = term;
    __syncthreads();

    if (c < 64) red[c] += red[c + 512];
    __syncthreads();
    for (int o = 256; o > 0; o >>= 1) {
        if (c < o) red[c] += red[c + o];
        __syncthreads();
    }
    if (c == 0) g_mi[b] = red[0];
}

__global__ void mi_final_kernel(float* __restrict__ out)
{
    double s = 0.0;
    for (int b = 0; b < BATCH; ++b) s += g_mi[b];
    out[0] = (float)(-s / (double)BATCH);
}

extern "C" void kernel_launch(void* const* d_in, const int* in_sizes, int n_in,
                              void* d_out, int out_size)
{
    (void)in_sizes; (void)n_in; (void)out_size;
    const float* pred   = (const float*)d_in[0];
    const float* target = (const float*)d_in[1];

    dim3 g1(NBLK, BATCH);
    mi_partial_kernel<<<g1, BLOCK_T>>>(pred, target);

    dim3 g2(18, BATCH);
    mi_reduce1_kernel<<<g2, 1024>>>();

    mi_reduce2_kernel<<<BATCH, CELLS>>>();

    mi_final_kernel<<<1, 1>>>((float*)d_out);
}

// round 3
// speedup vs baseline: 1.2754x; 1.2754x over previous
#include <cuda_runtime.h>
#include <math.h>

// Shapes fixed: pred/target = [4,1,96,96,96] fp32, out = scalar fp32.
#define NB      23
#define NBIN    24            // padded bins (bin 23 weight = 0)
#define SROW    28            // shared row stride in floats (16B-aligned, s4=7 odd)
#define BT      256           // threads/block
#define NGRP    32            // 8-thread groups per block
#define STAGES  48
#define VPB     (BT*STAGES)   // 12288 voxels per block
#define BPB     72            // blocks per batch: 72*12288 = 884736
#define BATCH   4
#define NVOX    884736
#define NCHUNK  (BPB*NGRP)    // 2304 partial chunks per batch
#define CELLS   (NBIN*NBIN)   // 576
#define KGRP    36            // reduce1 groups (64 chunks each)
#define K2EXP   (-1396.5287995805166f)   // -968 * log2(e)
#define SMEM_BYTES (2*BT*SROW*4)         // 57344

__device__ float  g_partial[(size_t)BATCH * NCHUNK * CELLS]; // 21.2 MB
__device__ double g_p2[BATCH * KGRP * CELLS];

__device__ __forceinline__ float ex2f(float x) {
    float r;
    asm("ex2.approx.ftz.f32 %0, %1;" : "=f"(r) : "f"(x));
    return r;
}
__device__ __forceinline__ unsigned long long dupf(float x) {
    unsigned long long r;
    unsigned u = __float_as_uint(x);
    asm("mov.b64 %0, {%1, %1};" : "=l"(r) : "r"(u));
    return r;
}
__device__ __forceinline__ void ffma2(unsigned long long& d,
                                      unsigned long long a,
                                      unsigned long long b) {
    asm("fma.rn.f32x2 %0, %1, %2, %0;" : "+l"(d) : "l"(a), "l"(b));
}

extern __shared__ float smemf[];   // [waS | wbS], each BT*SROW floats

__global__ __launch_bounds__(BT, 2)
void mi_main(const float* __restrict__ pred, const float* __restrict__ target)
{
    float* waS = smemf;
    float* wbS = smemf + BT * SROW;

    const int tid   = threadIdx.x;
    const int b     = blockIdx.y;
    const int blk   = blockIdx.x;
    const int g     = tid >> 3;          // group 0..31
    const int lane8 = tid & 7;
    const int gi    = lane8 & 3;         // i-tile: rows gi*6 .. gi*6+5
    const int gj    = lane8 >> 2;        // j-tile: cols gj*12 .. gj*12+11

    const float* __restrict__ px = pred   + (size_t)b * NVOX + (size_t)blk * VPB;
    const float* __restrict__ py = target + (size_t)b * NVOX + (size_t)blk * VPB;

    // 6x12 tile as 6x6 packed f32x2 accumulators (j-pairs)
    unsigned long long acc[6][6];
    #pragma unroll
    for (int i = 0; i < 6; ++i)
        #pragma unroll
        for (int j = 0; j < 6; ++j) acc[i][j] = 0ULL;

    for (int s = 0; s < STAGES; ++s) {
        const int idx = s * BT + tid;
        float x = px[idx]; x = fminf(fmaxf(x, 0.0f), 1.0f);
        float y = py[idx]; y = fminf(fmaxf(y, 0.0f), 1.0f);

        // --- generate wa (streamed by quads, unscaled) ---
        float Sa = 0.0f;
        #pragma unroll
        for (int q = 0; q < 6; ++q) {
            float w[4];
            #pragma unroll
            for (int r = 0; r < 4; ++r) {
                const int i = 4 * q + r;
                if (i < NB) {
                    const float d = x - (float)(i * (1.0 / 22.0));
                    w[r] = ex2f(K2EXP * d * d);
                    Sa += w[r];
                } else {
                    w[r] = 0.0f;
                }
            }
            *(float4*)&waS[tid * SROW + 4 * q] = make_float4(w[0], w[1], w[2], w[3]);
        }

        // --- generate wb (full array, then scale by 1/(Sa*Sb)) ---
        float wb[NBIN];
        float Sb = 0.0f;
        #pragma unroll
        for (int i = 0; i < NB; ++i) {
            const float d = y - (float)(i * (1.0 / 22.0));
            wb[i] = ex2f(K2EXP * d * d);
            Sb += wb[i];
        }
        wb[NB] = 0.0f;
        const float rs = 1.0f / (Sa * Sb);   // correctly-rounded reciprocal
        #pragma unroll
        for (int q = 0; q < 6; ++q)
            *(float4*)&wbS[tid * SROW + 4 * q] =
                make_float4(wb[4*q] * rs, wb[4*q+1] * rs, wb[4*q+2] * rs, wb[4*q+3] * rs);

        __syncthreads();

        // --- 6x12 outer-product accumulation; group g handles voxels v*32+g ---
        #pragma unroll 2
        for (int v = 0; v < 8; ++v) {
            const int t = v * NGRP + g;

            const float* war = &waS[t * SROW + gi * 6];
            const float2 a01 = *(const float2*)(war);
            const float2 a23 = *(const float2*)(war + 2);
            const float2 a45 = *(const float2*)(war + 4);
            unsigned long long A[6];
            A[0] = dupf(a01.x); A[1] = dupf(a01.y);
            A[2] = dupf(a23.x); A[3] = dupf(a23.y);
            A[4] = dupf(a45.x); A[5] = dupf(a45.y);

            const float* wbr = &wbS[t * SROW + gj * 12];
            const ulonglong2 b01 = *(const ulonglong2*)(wbr);
            const ulonglong2 b23 = *(const ulonglong2*)(wbr + 4);
            const ulonglong2 b45 = *(const ulonglong2*)(wbr + 8);
            unsigned long long Bv[6] = { b01.x, b01.y, b23.x, b23.y, b45.x, b45.y };

            #pragma unroll
            for (int ii = 0; ii < 6; ++ii)
                #pragma unroll
                for (int jp = 0; jp < 6; ++jp)
                    ffma2(acc[ii][jp], A[ii], Bv[jp]);
        }
        __syncthreads();
    }

    // write this group's 24x24 partial: layout [b][chunk][cell], chunk = blk*32+g
    float* outp = g_partial + ((size_t)b * NCHUNK + (size_t)blk * NGRP + g) * CELLS;
    #pragma unroll
    for (int ii = 0; ii < 6; ++ii)
        #pragma unroll
        for (int jp = 0; jp < 6; ++jp) {
            const int cell = (gi * 6 + ii) * NBIN + gj * 12 + 2 * jp;
            *(unsigned long long*)&outp[cell] = acc[ii][jp];   // {c_j, c_j+1}
        }
}

// Stage-1 reduce: block (kg,b) sums 64 chunks of 576 cells, coalesced over cells.
__global__ __launch_bounds__(CELLS)
void mi_reduce1()
{
    const int b  = blockIdx.y;
    const int kg = blockIdx.x;       // 0..35
    const int c  = threadIdx.x;      // 0..575
    const float* __restrict__ p = g_partial + ((size_t)b * NCHUNK + (size_t)kg * 64) * CELLS + c;
    float s = 0.0f;
    #pragma unroll 4
    for (int k = 0; k < 64; ++k) s += p[(size_t)k * CELLS];
    g_p2[((size_t)b * KGRP + kg) * CELLS + c] = (double)s;
}

// Stage-2: one block does everything else (marginals, MI, mean) in double.
__global__ __launch_bounds__(CELLS)
void mi_reduce2(float* __restrict__ out)
{
    __shared__ double pabS[CELLS];
    __shared__ double paS[NBIN], pbS[NBIN];
    __shared__ double red[CELLS];
    __shared__ double miS[BATCH];
    const int c = threadIdx.x;
    const double invN = 1.0 / (double)NVOX;

    for (int b = 0; b < BATCH; ++b) {
        double t = 0.0;
        for (int kg = 0; kg < KGRP; ++kg)
            t += g_p2[((size_t)b * KGRP + kg) * CELLS + c];
        pabS[c] = t;
        __syncthreads();

        if (c < NB) {
            double m = 0.0;
            for (int j = 0; j < NB; ++j) m += pabS[c * NBIN + j];
            paS[c] = m * invN;
        } else if (c >= 32 && c < 32 + NB) {
            const int j = c - 32;
            double m = 0.0;
            for (int i = 0; i < NB; ++i) m += pabS[i * NBIN + j];
            pbS[j] = m * invN;
        }
        __syncthreads();

        const int i = c / NBIN, j = c % NBIN;
        double term = 0.0;
        if (i < NB && j < NB) {
            const double pab  = pabS[c] * invN;
            const double papb = paS[i] * pbS[j];
            term = pab * log((pab + 1e-7) / (papb + 1e-7) + 1e-7);
        }
        red[c] = term;
        __syncthreads();

        if (c < 64) red[c] += red[c + 512];
        __syncthreads();
        for (int o = 256; o > 0; o >>= 1) {
            if (c < o) red[c] += red[c + o];
            __syncthreads();
        }
        if (c == 0) miS[b] = red[0];
        __syncthreads();
    }

    if (c == 0) {
        double s = 0.0;
        for (int b = 0; b < BATCH; ++b) s += miS[b];
        out[0] = (float)(-s / (double)BATCH);
    }
}

extern "C" void kernel_launch(void* const* d_in, const int* in_sizes, int n_in,
                              void* d_out, int out_size)
{
    (void)in_sizes; (void)n_in; (void)out_size;
    const float* pred   = (const float*)d_in[0];
    const float* target = (const float*)d_in[1];

    cudaFuncSetAttribute(mi_main, cudaFuncAttributeMaxDynamicSharedMemorySize, SMEM_BYTES);

    dim3 g1(BPB, BATCH);
    mi_main<<<g1, BT, SMEM_BYTES>>>(pred, target);

    dim3 g2(KGRP, BATCH);
    mi_reduce1<<<g2, CELLS>>>();

    mi_reduce2<<<1, CELLS>>>((float*)d_out);
}

// round 4
// speedup vs baseline: 1.6445x; 1.2894x over previous
#include <cuda_runtime.h>
#include <math.h>

// Shapes fixed: pred/target = [4,1,96,96,96] fp32, out = scalar fp32.
#define NB      23
#define NBIN    24            // padded bins (bin 23 weight = 0)
#define SROW    28            // shared row stride in floats (16B-aligned, 112B rows)
#define BT      256           // threads/block
#define NGRP    32            // 8-thread groups per block
#define STAGES  48
#define VPB     (BT*STAGES)   // 12288 voxels per block
#define BPB     72            // blocks per batch: 72*12288 = 884736
#define BATCH   4
#define NVOX    884736
#define CELLS   (NBIN*NBIN)   // 576
#define RROW    584           // group-reduction scratch row stride (floats)
#define K2EXP   (-1396.5287995805166f)   // -968 * log2(e)
#define ABUF    (BT*SROW)                // floats per weight array
#define SMEM_BYTES (4*ABUF*4)            // 114688 B (double-buffered wa/wb)

__device__ double g_bpart[(size_t)BATCH * BPB * CELLS];  // per-block partial pab, 1.33 MB
__device__ double g_mi[BATCH];

__device__ __forceinline__ float ex2f(float x) {
    float r;
    asm("ex2.approx.ftz.f32 %0, %1;" : "=f"(r) : "f"(x));
    return r;
}
__device__ __forceinline__ unsigned long long dupf(float x) {
    unsigned long long r;
    unsigned u = __float_as_uint(x);
    asm("mov.b64 %0, {%1, %1};" : "=l"(r) : "r"(u));
    return r;
}
__device__ __forceinline__ void ffma2(unsigned long long& d,
                                      unsigned long long a,
                                      unsigned long long b) {
    asm("fma.rn.f32x2 %0, %1, %2, %0;" : "+l"(d) : "l"(a), "l"(b));
}

extern __shared__ float smemf[];   // [waS0 | wbS0 | waS1 | wbS1]

// Generate Parzen weights for one voxel pair into shared row (tid-indexed).
__device__ __forceinline__ void gen_weights(float x, float y,
                                            float* __restrict__ waRow,
                                            float* __restrict__ wbRow)
{
    x = fminf(fmaxf(x, 0.0f), 1.0f);
    y = fminf(fmaxf(y, 0.0f), 1.0f);

    // wa: streamed by quads (unscaled)
    float Sa = 0.0f;
    #pragma unroll
    for (int q = 0; q < 6; ++q) {
        float w[4];
        #pragma unroll
        for (int r = 0; r < 4; ++r) {
            const int i = 4 * q + r;
            if (i < NB) {
                const float d = x - (float)(i * (1.0 / 22.0));
                w[r] = ex2f(K2EXP * d * d);
                Sa += w[r];
            } else {
                w[r] = 0.0f;
            }
        }
        *(float4*)&waRow[4 * q] = make_float4(w[0], w[1], w[2], w[3]);
    }

    // wb: full array, then scale by 1/(Sa*Sb)
    float wb[NBIN];
    float Sb = 0.0f;
    #pragma unroll
    for (int i = 0; i < NB; ++i) {
        const float d = y - (float)(i * (1.0 / 22.0));
        wb[i] = ex2f(K2EXP * d * d);
        Sb += wb[i];
    }
    wb[NB] = 0.0f;
    const float rs = 1.0f / (Sa * Sb);   // correctly-rounded reciprocal
    #pragma unroll
    for (int q = 0; q < 6; ++q)
        *(float4*)&wbRow[4 * q] =
            make_float4(wb[4*q] * rs, wb[4*q+1] * rs, wb[4*q+2] * rs, wb[4*q+3] * rs);
}

__global__ __launch_bounds__(BT, 2)
void mi_main(const float* __restrict__ pred, const float* __restrict__ target)
{
    float* const waB[2] = { smemf,            smemf + 2 * ABUF };
    float* const wbB[2] = { smemf + ABUF,     smemf + 3 * ABUF };

    const int tid   = threadIdx.x;
    const int b     = blockIdx.y;
    const int blk   = blockIdx.x;
    const int g     = tid >> 3;          // group 0..31
    const int lane8 = tid & 7;
    const int gi    = lane8 & 3;         // i-tile: rows gi*6 .. gi*6+5
    const int gj    = lane8 >> 2;        // j-tile: cols gj*12 .. gj*12+11

    const float* __restrict__ px = pred   + (size_t)b * NVOX + (size_t)blk * VPB;
    const float* __restrict__ py = target + (size_t)b * NVOX + (size_t)blk * VPB;

    // 6x12 tile as 6x6 packed f32x2 accumulators (fp32 over 384 voxels)
    unsigned long long acc[6][6];
    #pragma unroll
    for (int i = 0; i < 6; ++i)
        #pragma unroll
        for (int j = 0; j < 6; ++j) acc[i][j] = 0ULL;

    // prologue: stage 0 weights into buffer 0
    gen_weights(px[tid], py[tid], &waB[0][tid * SROW], &wbB[0][tid * SROW]);
    __syncthreads();

    for (int s = 0; s < STAGES; ++s) {
        const int p = s & 1;

        // produce next stage into the other buffer (overlaps with MMA below)
        if (s + 1 < STAGES) {
            const int idx = (s + 1) * BT + tid;
            gen_weights(px[idx], py[idx],
                        &waB[p ^ 1][tid * SROW], &wbB[p ^ 1][tid * SROW]);
        }

        // consume current buffer: 6x12 outer-product per thread
        const float* __restrict__ waS = waB[p];
        const float* __restrict__ wbS = wbB[p];
        #pragma unroll 2
        for (int v = 0; v < 8; ++v) {
            const int t = v * NGRP + g;

            const float* war = &waS[t * SROW + gi * 6];
            const float2 a01 = *(const float2*)(war);
            const float2 a23 = *(const float2*)(war + 2);
            const float2 a45 = *(const float2*)(war + 4);
            unsigned long long A[6];
            A[0] = dupf(a01.x); A[1] = dupf(a01.y);
            A[2] = dupf(a23.x); A[3] = dupf(a23.y);
            A[4] = dupf(a45.x); A[5] = dupf(a45.y);

            const float* wbr = &wbS[t * SROW + gj * 12];
            const ulonglong2 b01 = *(const ulonglong2*)(wbr);
            const ulonglong2 b23 = *(const ulonglong2*)(wbr + 4);
            const ulonglong2 b45 = *(const ulonglong2*)(wbr + 8);
            unsigned long long Bv[6] = { b01.x, b01.y, b23.x, b23.y, b45.x, b45.y };

            #pragma unroll
            for (int ii = 0; ii < 6; ++ii)
                #pragma unroll
                for (int jp = 0; jp < 6; ++jp)
                    ffma2(acc[ii][jp], A[ii], Bv[jp]);
        }
        __syncthreads();
    }

    // ---- in-block reduction of the 32 group tiles (reuse smem as scratch) ----
    float* sred = smemf;   // 32 * RROW * 4 = 74752 B <= 114688 B
    #pragma unroll
    for (int ii = 0; ii < 6; ++ii)
        #pragma unroll
        for (int jp = 0; jp < 6; ++jp) {
            const int cell = (gi * 6 + ii) * NBIN + gj * 12 + 2 * jp;
            *(unsigned long long*)&sred[g * RROW + cell] = acc[ii][jp];
        }
    __syncthreads();

    double* outp = g_bpart + ((size_t)b * BPB + blk) * CELLS;
    for (int c = tid; c < CELLS; c += BT) {
        float ssum = 0.0f;
        #pragma unroll 8
        for (int g2 = 0; g2 < NGRP; ++g2) ssum += sred[g2 * RROW + c];
        outp[c] = (double)ssum;
    }
}

// Per-batch: sum 72 block partials, marginals, MI — all in double. Grid = 4.
__global__ __launch_bounds__(CELLS)
void mi_batch()
{
    __shared__ double pabS[CELLS];
    __shared__ double paS[NBIN], pbS[NBIN];
    __shared__ double red[CELLS];
    const int b = blockIdx.x;
    const int c = threadIdx.x;
    const double invN = 1.0 / (double)NVOX;

    double t = 0.0;
    #pragma unroll 4
    for (int blk = 0; blk < BPB; ++blk)
        t += g_bpart[((size_t)b * BPB + blk) * CELLS + c];
    pabS[c] = t;
    __syncthreads();

    if (c < NB) {
        double m = 0.0;
        for (int j = 0; j < NB; ++j) m += pabS[c * NBIN + j];
        paS[c] = m * invN;
    } else if (c >= 32 && c < 32 + NB) {
        const int j = c - 32;
        double m = 0.0;
        for (int i = 0; i < NB; ++i) m += pabS[i * NBIN + j];
        pbS[j] = m * invN;
    }
    __syncthreads();

    const int i = c / NBIN, j = c % NBIN;
    double term = 0.0;
    if (i < NB && j < NB) {
        const double pab  = pabS[c] * invN;
        const double papb = paS[i] * pbS[j];
        term = pab * log((pab + 1e-7) / (papb + 1e-7) + 1e-7);
    }
    red[c] = term;
    __syncthreads();

    if (c < 64) red[c] += red[c + 512];
    __syncthreads();
    for (int o = 256; o > 0; o >>= 1) {
        if (c < o) red[c] += red[c + o];
        __syncthreads();
    }
    if (c == 0) g_mi[b] = red[0];
}

__global__ void mi_final(float* __restrict__ out)
{
    double s = 0.0;
    for (int b = 0; b < BATCH; ++b) s += g_mi[b];
    out[0] = (float)(-s / (double)BATCH);
}

extern "C" void kernel_launch(void* const* d_in, const int* in_sizes, int n_in,
                              void* d_out, int out_size)
{
    (void)in_sizes; (void)n_in; (void)out_size;
    const float* pred   = (const float*)d_in[0];
    const float* target = (const float*)d_in[1];

    cudaFuncSetAttribute(mi_main, cudaFuncAttributeMaxDynamicSharedMemorySize, SMEM_BYTES);

    dim3 g1(BPB, BATCH);
    mi_main<<<g1, BT, SMEM_BYTES>>>(pred, target);

    mi_batch<<<BATCH, CELLS>>>();

    mi_final<<<1, 1>>>((float*)d_out);
}

// round 5
// speedup vs baseline: 1.7631x; 1.0721x over previous
#include <cuda_runtime.h>
#include <math.h>

// Shapes fixed: pred/target = [4,1,96,96,96] fp32, out = scalar fp32.
#define NB      23
#define NBIN    24            // padded bins (bin 23 weight = 0)
#define SROW    28            // shared row stride in floats (16B-aligned, 112B rows)
#define BT      256           // threads/block
#define NGRP    16            // 16-thread groups per block (4x4 over 24x24, 6x6 tiles)
#define STAGES  32
#define VPB     (BT*STAGES)   // 8192 voxels per block
#define BPB     108           // blocks per batch: 108*8192 = 884736
#define BATCH   4
#define NVOX    884736
#define CELLS   (NBIN*NBIN)   // 576
#define RROW    584           // group-reduction scratch row stride (floats)
#define K2EXP   (-1396.5287995805166f)   // -968 * log2(e)
#define ABUF    (BT*SROW)                // floats per weight array (7168)
#define SMEM_BYTES (2*ABUF*4)            // 57344 B (single-buffered wa/wb)

__device__ double g_bpart[(size_t)BATCH * BPB * CELLS];  // per-block partial pab, ~2 MB
__device__ double g_mi[BATCH];

__device__ __forceinline__ float ex2f(float x) {
    float r;
    asm("ex2.approx.ftz.f32 %0, %1;" : "=f"(r) : "f"(x));
    return r;
}
__device__ __forceinline__ unsigned long long dupf(float x) {
    unsigned long long r;
    unsigned u = __float_as_uint(x);
    asm("mov.b64 %0, {%1, %1};" : "=l"(r) : "r"(u));
    return r;
}
__device__ __forceinline__ void ffma2(unsigned long long& d,
                                      unsigned long long a,
                                      unsigned long long b) {
    asm("fma.rn.f32x2 %0, %1, %2, %0;" : "+l"(d) : "l"(a), "l"(b));
}

extern __shared__ float smemf[];   // [waS | wbS] (also reused as reduction scratch)

__global__ __launch_bounds__(BT, 3)
void mi_main(const float* __restrict__ pred, const float* __restrict__ target)
{
    float* waS = smemf;
    float* wbS = smemf + ABUF;

    const int tid    = threadIdx.x;
    const int b      = blockIdx.y;
    const int blk    = blockIdx.x;
    const int g      = tid >> 4;          // group 0..15
    const int lane16 = tid & 15;
    const int gi     = lane16 & 3;        // i-tile: rows gi*6 .. gi*6+5
    const int gj     = lane16 >> 2;       // j-tile: cols gj*6 .. gj*6+5

    const float* __restrict__ px = pred   + (size_t)b * NVOX + (size_t)blk * VPB;
    const float* __restrict__ py = target + (size_t)b * NVOX + (size_t)blk * VPB;

    // 6x6 tile as 6x3 packed f32x2 accumulators (j-pairs)
    unsigned long long acc[6][3];
    #pragma unroll
    for (int i = 0; i < 6; ++i)
        #pragma unroll
        for (int j = 0; j < 3; ++j) acc[i][j] = 0ULL;

    for (int s = 0; s < STAGES; ++s) {
        // ---------- gen phase ----------
        {
            const int idx = s * BT + tid;
            float x = px[idx]; x = fminf(fmaxf(x, 0.0f), 1.0f);
            float y = py[idx]; y = fminf(fmaxf(y, 0.0f), 1.0f);

            // wa: streamed by quads, stored raw (unscaled)
            float Sa = 0.0f;
            #pragma unroll
            for (int q = 0; q < 6; ++q) {
                float w[4];
                #pragma unroll
                for (int r = 0; r < 4; ++r) {
                    const int i = 4 * q + r;
                    if (i < NB) {
                        const float d = x - (float)(i * (1.0 / 22.0));
                        w[r] = ex2f(K2EXP * d * d);
                    } else {
                        w[r] = 0.0f;
                    }
                }
                Sa += ((w[0] + w[1]) + (w[2] + w[3]));
                *(float4*)&waS[tid * SROW + 4 * q] = make_float4(w[0], w[1], w[2], w[3]);
            }

            // wb: streamed by quads, stored raw; Sb summed on the fly
            float Sb = 0.0f;
            #pragma unroll
            for (int q = 0; q < 6; ++q) {
                float w[4];
                #pragma unroll
                for (int r = 0; r < 4; ++r) {
                    const int i = 4 * q + r;
                    if (i < NB) {
                        const float d = y - (float)(i * (1.0 / 22.0));
                        w[r] = ex2f(K2EXP * d * d);
                    } else {
                        w[r] = 0.0f;
                    }
                }
                Sb += ((w[0] + w[1]) + (w[2] + w[3]));
                *(float4*)&wbS[tid * SROW + 4 * q] = make_float4(w[0], w[1], w[2], w[3]);
            }

            // rescale wb in place by 1/(Sa*Sb) (correctly-rounded reciprocal)
            const float rs = 1.0f / (Sa * Sb);
            #pragma unroll
            for (int q = 0; q < 6; ++q) {
                float4 v = *(float4*)&wbS[tid * SROW + 4 * q];
                v.x *= rs; v.y *= rs; v.z *= rs; v.w *= rs;
                *(float4*)&wbS[tid * SROW + 4 * q] = v;
            }
        }
        __syncthreads();

        // ---------- MMA phase: 6x6 outer-product; group g handles voxels v*16+g ----------
        #pragma unroll 4
        for (int v = 0; v < 16; ++v) {
            const int t = v * NGRP + g;

            const float* war = &waS[t * SROW + gi * 6];
            const float2 a01 = *(const float2*)(war);
            const float2 a23 = *(const float2*)(war + 2);
            const float2 a45 = *(const float2*)(war + 4);
            unsigned long long A[6];
            A[0] = dupf(a01.x); A[1] = dupf(a01.y);
            A[2] = dupf(a23.x); A[3] = dupf(a23.y);
            A[4] = dupf(a45.x); A[5] = dupf(a45.y);

            const float* wbr = &wbS[t * SROW + gj * 6];
            unsigned long long Bv[3];
            Bv[0] = *(const unsigned long long*)(wbr);
            Bv[1] = *(const unsigned long long*)(wbr + 2);
            Bv[2] = *(const unsigned long long*)(wbr + 4);

            #pragma unroll
            for (int ii = 0; ii < 6; ++ii)
                #pragma unroll
                for (int jp = 0; jp < 3; ++jp)
                    ffma2(acc[ii][jp], A[ii], Bv[jp]);
        }
        __syncthreads();
    }

    // ---- in-block reduction of the 16 group tiles (reuse smem as scratch) ----
    float* sred = smemf;   // 16 * RROW * 4 = 37376 B <= 57344 B
    #pragma unroll
    for (int ii = 0; ii < 6; ++ii)
        #pragma unroll
        for (int jp = 0; jp < 3; ++jp) {
            const int cell = (gi * 6 + ii) * NBIN + gj * 6 + 2 * jp;
            *(unsigned long long*)&sred[g * RROW + cell] = acc[ii][jp];
        }
    __syncthreads();

    double* outp = g_bpart + ((size_t)b * BPB + blk) * CELLS;
    for (int c = tid; c < CELLS; c += BT) {
        float ssum = 0.0f;
        #pragma unroll
        for (int g2 = 0; g2 < NGRP; ++g2) ssum += sred[g2 * RROW + c];
        outp[c] = (double)ssum;
    }
}

// Per-batch: sum 108 block partials, marginals, MI — all in double. Grid = 4.
__global__ __launch_bounds__(CELLS)
void mi_batch()
{
    __shared__ double pabS[CELLS];
    __shared__ double paS[NBIN], pbS[NBIN];
    __shared__ double red[CELLS];
    const int b = blockIdx.x;
    const int c = threadIdx.x;
    const double invN = 1.0 / (double)NVOX;

    double t = 0.0;
    #pragma unroll 4
    for (int blk = 0; blk < BPB; ++blk)
        t += g_bpart[((size_t)b * BPB + blk) * CELLS + c];
    pabS[c] = t;
    __syncthreads();

    if (c < NB) {
        double m = 0.0;
        for (int j = 0; j < NB; ++j) m += pabS[c * NBIN + j];
        paS[c] = m * invN;
    } else if (c >= 32 && c < 32 + NB) {
        const int j = c - 32;
        double m = 0.0;
        for (int i = 0; i < NB; ++i) m += pabS[i * NBIN + j];
        pbS[j] = m * invN;
    }
    __syncthreads();

    const int i = c / NBIN, j = c % NBIN;
    double term = 0.0;
    if (i < NB && j < NB) {
        const double pab  = pabS[c] * invN;
        const double papb = paS[i] * pbS[j];
        term = pab * log((pab + 1e-7) / (papb + 1e-7) + 1e-7);
    }
    red[c] = term;
    __syncthreads();

    if (c < 64) red[c] += red[c + 512];
    __syncthreads();
    for (int o = 256; o > 0; o >>= 1) {
        if (c < o) red[c] += red[c + o];
        __syncthreads();
    }
    if (c == 0) g_mi[b] = red[0];
}

__global__ void mi_final(float* __restrict__ out)
{
    double s = 0.0;
    for (int b = 0; b < BATCH; ++b) s += g_mi[b];
    out[0] = (float)(-s / (double)BATCH);
}

extern "C" void kernel_launch(void* const* d_in, const int* in_sizes, int n_in,
                              void* d_out, int out_size)
{
    (void)in_sizes; (void)n_in; (void)out_size;
    const float* pred   = (const float*)d_in[0];
    const float* target = (const float*)d_in[1];

    cudaFuncSetAttribute(mi_main, cudaFuncAttributeMaxDynamicSharedMemorySize, SMEM_BYTES);

    dim3 g1(BPB, BATCH);
    mi_main<<<g1, BT, SMEM_BYTES>>>(pred, target);

    mi_batch<<<BATCH, CELLS>>>();

    mi_final<<<1, 1>>>((float*)d_out);
}